// round 13
// baseline (speedup 1.0000x reference)
#include <cuda_runtime.h>
#include <cuda_bf16.h>
#include <math.h>

// Problem constants
#define BATCH 4
#define SEQ   2048
#define EMB   1024
#define HEADS 16
#define HDIM  64
#define MROWS (BATCH*SEQ)   // 8192

// ---------------- scratch (device globals; no allocation allowed) -------------
__device__ float g_q[BATCH*HEADS*SEQ*HDIM];    // [B,H,S,D] interleaved d, pre-scaled
__device__ float g_k[BATCH*HEADS*SEQ*HDIM];    // [B,H,S,D] interleaved d
__device__ float g_v[BATCH*HEADS*SEQ*HDIM];    // [B,H,S,D] natural
__device__ float g_ctx[BATCH*SEQ*EMB];         // [B,S,E]   pre-rounded
__device__ float g_xr[MROWS*EMB];              // x, tf32-rounded
__device__ float g_wr[4*EMB*EMB];              // Wq,Wk,Wv,Wo tf32-rounded

// ---------------- helpers ------------------------------------------------------
__device__ __forceinline__ unsigned f2tf(float x) {
    unsigned u;
    asm("cvt.rna.tf32.f32 %0, %1;" : "=r"(u) : "f"(x));
    return u;
}
__device__ __forceinline__ float f2tff(float x) {
    return __uint_as_float(f2tf(x));
}
__device__ __forceinline__ float ex2f(float x) {
    float y;
    asm("ex2.approx.f32 %0, %1;" : "=f"(y) : "f"(x));
    return y;
}
__device__ __forceinline__ void mma8(float c[4], const unsigned a[4], const unsigned b[2]) {
    asm volatile(
        "mma.sync.aligned.m16n8k8.row.col.f32.tf32.tf32.f32 "
        "{%0,%1,%2,%3}, {%4,%5,%6,%7}, {%8,%9}, {%0,%1,%2,%3};"
        : "+f"(c[0]), "+f"(c[1]), "+f"(c[2]), "+f"(c[3])
        : "r"(a[0]), "r"(a[1]), "r"(a[2]), "r"(a[3]),
          "r"(b[0]), "r"(b[1]));
}
__device__ __forceinline__ void cpa16(unsigned smem, const void* gmem) {
    asm volatile("cp.async.cg.shared.global [%0], [%1], 16;" :: "r"(smem), "l"(gmem));
}
__device__ __forceinline__ void cpa_commit() {
    asm volatile("cp.async.commit_group;");
}
__device__ __forceinline__ void cpa_wait1() {
    asm volatile("cp.async.wait_group 1;");
}
__device__ __forceinline__ void cpa_wait0() {
    asm volatile("cp.async.wait_group 0;");
}

// ---------------- pre-round kernels --------------------------------------------
__global__ __launch_bounds__(256) void roundcpy(
    const float4* __restrict__ src, float4* __restrict__ dst, int n4)
{
    int i = blockIdx.x * blockDim.x + threadIdx.x;
    int stride = gridDim.x * blockDim.x;
    for (; i < n4; i += stride) {
        float4 v = src[i];
        v.x = f2tff(v.x); v.y = f2tff(v.y);
        v.z = f2tff(v.z); v.w = f2tff(v.w);
        dst[i] = v;
    }
}

// One launch for all 4 weight matrices (dst contiguous in g_wr)
__global__ __launch_bounds__(256) void roundcpy4(
    const float4* __restrict__ s0, const float4* __restrict__ s1,
    const float4* __restrict__ s2, const float4* __restrict__ s3,
    float4* __restrict__ dst, int n4each)
{
    int i = blockIdx.x * blockDim.x + threadIdx.x;
    int stride = gridDim.x * blockDim.x;
    const int total = 4 * n4each;
    for (; i < total; i += stride) {
        int wsel = i / n4each;
        int off  = i - wsel * n4each;
        const float4* s = (wsel == 0) ? s0 : (wsel == 1) ? s1 : (wsel == 2) ? s2 : s3;
        float4 v = s[off];
        v.x = f2tff(v.x); v.y = f2tff(v.y);
        v.z = f2tff(v.z); v.w = f2tff(v.w);
        dst[i] = v;
    }
}

// ---------------- GEMM (tf32 MMA, cp.async 2-stage): C = A @ W + bias ---------
// Inputs pre-rounded. mode: 0 = plain row-major fp32 out;
// 1 = qkv scatter, d interleaved (pair-perm), scaled+rounded (Q/K);
// 2 = qkv scatter, natural d, rounded (V).
#define AST 36
#define BST 136
#define NKT (EMB / 32)   // 32 k-tiles
#define QSCALE 0.1803368801f    // (1/8) * log2(e)

__global__ __launch_bounds__(256, 2) void gemm_tf32(
    const float* __restrict__ A, const float* __restrict__ W,
    const float* __restrict__ bias, float* __restrict__ C,
    int mode, float scale)
{
    __shared__ float As[2][128 * AST];
    __shared__ float Bs[2][32 * BST];

    const int tid  = threadIdx.x;
    const int lane = tid & 31;
    const int wid  = tid >> 5;
    const int wr   = wid >> 2;      // 0..1
    const int wc   = wid & 3;       // 0..3
    const int g    = lane >> 2;     // 0..7
    const int q    = lane & 3;      // 0..3
    const int rowBase = blockIdx.y * 128;
    const int colBase = blockIdx.x * 128;

    const float* Ag = A + (size_t)rowBase * EMB;
    const float* Wg = W + colBase;

    // Per-thread staging coordinates (fixed across tiles)
    const int ar  = tid >> 1;            // A row 0..127 (two threads per row)
    const int ac4 = (tid & 1) * 4;       // A float4 col: handles c4 and c4+... below
    const int br  = tid >> 5;            // B k-row 0..7 (covers 8 rows; 4 iters cover 32)
    const int bc4 = tid & 31;            // B float4 col 0..31

    unsigned as_a[2], bs_a[2];
    as_a[0] = (unsigned)__cvta_generic_to_shared(&As[0][0]);
    as_a[1] = (unsigned)__cvta_generic_to_shared(&As[1][0]);
    bs_a[0] = (unsigned)__cvta_generic_to_shared(&Bs[0][0]);
    bs_a[1] = (unsigned)__cvta_generic_to_shared(&Bs[1][0]);

    // Issue loads for k-tile kt into stage st
    auto load_tile = [&](int kt, int st) {
        // A tile 128x32: 1024 float4 -> 4 per thread
#pragma unroll
        for (int i = 0; i < 4; i++) {
            int f  = tid + i * 256;
            int r  = f >> 3;
            int c4 = f & 7;
            cpa16(as_a[st] + (r * AST + c4 * 4) * 4,
                  Ag + (size_t)r * EMB + kt * 32 + c4 * 4);
        }
        // W tile 32x128: 1024 float4 -> 4 per thread
#pragma unroll
        for (int i = 0; i < 4; i++) {
            int f  = tid + i * 256;
            int r  = f >> 5;
            int c4 = f & 31;
            cpa16(bs_a[st] + (r * BST + c4 * 4) * 4,
                  Wg + (size_t)(kt * 32 + r) * EMB + c4 * 4);
        }
        cpa_commit();
    };

    float acc[4][4][4];
#pragma unroll
    for (int mt = 0; mt < 4; mt++)
#pragma unroll
        for (int nt = 0; nt < 4; nt++)
#pragma unroll
            for (int i = 0; i < 4; i++) acc[mt][nt][i] = 0.f;

    load_tile(0, 0);

    for (int t = 0; t < NKT; t++) {
        const int st = t & 1;
        if (t + 1 < NKT) {
            load_tile(t + 1, st ^ 1);
            cpa_wait1();
        } else {
            cpa_wait0();
        }
        __syncthreads();

        const float* Asb = As[st];
        const float* Bsb = Bs[st];
#pragma unroll
        for (int kk = 0; kk < 4; kk++) {
            const int k0 = kk * 8;
            unsigned a[4][4], b[4][2];
#pragma unroll
            for (int mt = 0; mt < 4; mt++) {
                int row = wr * 64 + mt * 16 + g;
                const float* p = &Asb[row * AST + k0 + q];
                a[mt][0] = __float_as_uint(p[0]);
                a[mt][1] = __float_as_uint(p[8 * AST]);
                a[mt][2] = __float_as_uint(p[4]);
                a[mt][3] = __float_as_uint(p[8 * AST + 4]);
            }
#pragma unroll
            for (int nt = 0; nt < 4; nt++) {
                int col = wc * 32 + nt * 8 + g;
                const float* p = &Bsb[(k0 + q) * BST + col];
                b[nt][0] = __float_as_uint(p[0]);
                b[nt][1] = __float_as_uint(p[4 * BST]);
            }
#pragma unroll
            for (int mt = 0; mt < 4; mt++)
#pragma unroll
                for (int nt = 0; nt < 4; nt++)
                    mma8(acc[mt][nt], a[mt], b[nt]);
        }
        __syncthreads();
    }

#pragma unroll
    for (int mt = 0; mt < 4; mt++) {
#pragma unroll
        for (int nt = 0; nt < 4; nt++) {
            int row = rowBase + wr * 64 + mt * 16 + g;
            int col = colBase + wc * 32 + nt * 8 + 2 * q;
            float e00 = acc[mt][nt][0] + bias[col];
            float e01 = acc[mt][nt][1] + bias[col + 1];
            float e10 = acc[mt][nt][2] + bias[col];
            float e11 = acc[mt][nt][3] + bias[col + 1];
            if (mode == 0) {
                float* base = C + (size_t)row * EMB + col;
                *(float2*)base = make_float2(e00, e01);
                *(float2*)(base + 8 * EMB) = make_float2(e10, e11);
            } else {
                e00 = f2tff(e00 * scale); e01 = f2tff(e01 * scale);
                e10 = f2tff(e10 * scale); e11 = f2tff(e11 * scale);
                int b0_ = row >> 11;
                int s0  = row & (SEQ - 1);
                int h   = col >> 6;
                int d   = col & (HDIM - 1);
                float* base = C + ((size_t)((b0_ * HEADS + h) * SEQ + s0)) * HDIM;
                if (mode == 1) {
                    // interleave perm within 8-group: w -> 2*(w&3) + (w>>2)
                    int grp = d & ~7;
                    int w0 = d & 7, w1 = w0 + 1;
                    int sl0 = grp + 2 * (w0 & 3) + (w0 >> 2);
                    int sl1 = grp + 2 * (w1 & 3) + (w1 >> 2);
                    base[sl0] = e00;             base[sl1] = e01;
                    base[8 * HDIM + sl0] = e10;  base[8 * HDIM + sl1] = e11;
                } else {
                    *(float2*)(base + d) = make_float2(e00, e01);
                    *(float2*)(base + 8 * HDIM + d) = make_float2(e10, e11);
                }
            }
        }
    }
}

// ---------------- Flash attention (tf32 MMA, v6 — unchanged) -------------------
#define QST 72
#define KST 72
#define VST 68
#define ATTN_SMEM ((128*QST + 2*64*KST + 2*64*VST) * 4)   // 108544 B

__global__ __launch_bounds__(128) void attn_mma(
    const float* __restrict__ Q, const float* __restrict__ K,
    const float* __restrict__ V, float* __restrict__ O)
{
    extern __shared__ float sm[];
    float* Qs  = sm;                      // [128][QST]
    float* Kb0 = Qs + 128 * QST;          // [64][KST]
    float* Kb1 = Kb0 + 64 * KST;
    float* Vb0 = Kb1 + 64 * KST;          // [64][VST]
    float* Vb1 = Vb0 + 64 * VST;

    const int tid  = threadIdx.x;
    const int lane = tid & 31;
    const int w    = tid >> 5;        // warp 0..3 -> rows w*32..w*32+31
    const int g    = lane >> 2;       // 0..7
    const int q    = lane & 3;        // 0..3
    const int bh   = blockIdx.y;      // 0..63
    const int qBase = blockIdx.x * 128;
    const unsigned FULL = 0xffffffffu;

    const float* Qg = Q + ((size_t)bh * SEQ + qBase) * HDIM;
    const float* Kg = K + (size_t)bh * SEQ * HDIM;
    const float* Vg = V + (size_t)bh * SEQ * HDIM;

    const unsigned qs_a  = (unsigned)__cvta_generic_to_shared(Qs);
    const unsigned kb_a[2] = { (unsigned)__cvta_generic_to_shared(Kb0),
                               (unsigned)__cvta_generic_to_shared(Kb1) };
    const unsigned vb_a[2] = { (unsigned)__cvta_generic_to_shared(Vb0),
                               (unsigned)__cvta_generic_to_shared(Vb1) };

    // Q tile: 128x64 = 2048 16B chunks; 16 per thread
#pragma unroll
    for (int i = 0; i < 16; i++) {
        int f  = tid + i * 128;
        int r  = f >> 4;
        int c4 = f & 15;
        cpa16(qs_a + (r * QST + c4 * 4) * 4, Qg + (size_t)r * HDIM + c4 * 4);
    }
    // K/V tile 0
    {
        const float* kb = Kg;
        const float* vb = Vg;
#pragma unroll
        for (int i = 0; i < 8; i++) {
            int f  = tid + i * 128;
            int r  = f >> 4;
            int c4 = f & 15;
            cpa16(kb_a[0] + (r * KST + c4 * 4) * 4, kb + (size_t)r * HDIM + c4 * 4);
            cpa16(vb_a[0] + (r * VST + c4 * 4) * 4, vb + (size_t)r * HDIM + c4 * 4);
        }
    }
    cpa_commit();

    float o[2][8][4];
#pragma unroll
    for (int mt = 0; mt < 2; mt++)
#pragma unroll
        for (int nt = 0; nt < 8; nt++)
#pragma unroll
            for (int i = 0; i < 4; i++) o[mt][nt][i] = 0.f;
    float l[2][2] = {{0.f, 0.f}, {0.f, 0.f}};   // [mt][row-half]

    for (int t = 0; t < SEQ / 64; t++) {
        if (t < SEQ / 64 - 1) {
            const int nb = (t + 1) & 1;
            const float* kb = Kg + (size_t)(t + 1) * 64 * HDIM;
            const float* vb = Vg + (size_t)(t + 1) * 64 * HDIM;
#pragma unroll
            for (int i = 0; i < 8; i++) {
                int f  = tid + i * 128;
                int r  = f >> 4;
                int c4 = f & 15;
                cpa16(kb_a[nb] + (r * KST + c4 * 4) * 4, kb + (size_t)r * HDIM + c4 * 4);
                cpa16(vb_a[nb] + (r * VST + c4 * 4) * 4, vb + (size_t)r * HDIM + c4 * 4);
            }
            cpa_commit();
            cpa_wait1();
        } else {
            cpa_wait0();
        }
        __syncthreads();

        const float* Ks = (t & 1) ? Kb1 : Kb0;
        const float* Vs = (t & 1) ? Vb1 : Vb0;

        // ---- S = Qscaled @ K^T : 32 rows x 64 cols per warp ----
        float s[2][8][4];
#pragma unroll
        for (int mt = 0; mt < 2; mt++)
#pragma unroll
            for (int nt = 0; nt < 8; nt++)
#pragma unroll
                for (int i = 0; i < 4; i++) s[mt][nt][i] = 0.f;

#pragma unroll
        for (int kk = 0; kk < 8; kk++) {
            const int sl = kk * 8 + 2 * q;
            unsigned a[2][4];
#pragma unroll
            for (int mt = 0; mt < 2; mt++) {
                const int row = w * 32 + mt * 16 + g;
                float2 x0 = *(const float2*)&Qs[row * QST + sl];
                float2 x1 = *(const float2*)&Qs[(row + 8) * QST + sl];
                a[mt][0] = __float_as_uint(x0.x);
                a[mt][1] = __float_as_uint(x1.x);
                a[mt][2] = __float_as_uint(x0.y);
                a[mt][3] = __float_as_uint(x1.y);
            }
#pragma unroll
            for (int nt = 0; nt < 8; nt++) {
                float2 kv = *(const float2*)&Ks[(nt * 8 + g) * KST + sl];
                unsigned b[2];
                b[0] = __float_as_uint(kv.x);
                b[1] = __float_as_uint(kv.y);
                mma8(s[0][nt], a[0], b);
                mma8(s[1][nt], a[1], b);
            }
        }

        // ---- P = ex2(S); O += P @ V (C-frag == A-frag, no shuffles) ----
        float rs[2][2] = {{0.f, 0.f}, {0.f, 0.f}};
#pragma unroll
        for (int kk = 0; kk < 8; kk++) {
            const int t0 = kk * 8;
            unsigned a[2][4];
#pragma unroll
            for (int mt = 0; mt < 2; mt++) {
                float p0 = ex2f(s[mt][kk][0]);   // (row g,   t 2q)
                float p1 = ex2f(s[mt][kk][1]);   // (row g,   t 2q+1)
                float p2 = ex2f(s[mt][kk][2]);   // (row g+8, t 2q)
                float p3 = ex2f(s[mt][kk][3]);   // (row g+8, t 2q+1)
                rs[mt][0] += p0 + p1;
                rs[mt][1] += p2 + p3;
                a[mt][0] = f2tf(p0);
                a[mt][1] = f2tf(p2);
                a[mt][2] = f2tf(p1);
                a[mt][3] = f2tf(p3);
            }
#pragma unroll
            for (int nt = 0; nt < 8; nt++) {
                const int col = nt * 8 + g;
                unsigned b[2];
                b[0] = __float_as_uint(Vs[(t0 + 2 * q)     * VST + col]);
                b[1] = __float_as_uint(Vs[(t0 + 2 * q + 1) * VST + col]);
                mma8(o[0][nt], a[0], b);
                mma8(o[1][nt], a[1], b);
            }
        }

        // accumulate row sums (quad reduction)
#pragma unroll
        for (int mt = 0; mt < 2; mt++) {
#pragma unroll
            for (int hh = 0; hh < 2; hh++) {
                float r_ = rs[mt][hh];
                r_ += __shfl_xor_sync(FULL, r_, 1);
                r_ += __shfl_xor_sync(FULL, r_, 2);
                l[mt][hh] += r_;
            }
        }
        __syncthreads();   // all warps done with this buffer before its refill
    }

    // Write context in [B,S,E] layout, pre-rounded for the O-projection GEMM
    const int b_ = bh >> 4;
    const int h  = bh & 15;
#pragma unroll
    for (int mt = 0; mt < 2; mt++) {
        const float inv0 = 1.0f / l[mt][0];
        const float inv1 = 1.0f / l[mt][1];
        const int srow = qBase + w * 32 + mt * 16 + g;
        float* dst0 = O + ((size_t)(b_ * SEQ + srow)) * EMB + h * HDIM;
        float* dst1 = dst0 + (size_t)8 * EMB;
#pragma unroll
        for (int nt = 0; nt < 8; nt++) {
            float2 v0, v1;
            v0.x = f2tff(o[mt][nt][0] * inv0); v0.y = f2tff(o[mt][nt][1] * inv0);
            v1.x = f2tff(o[mt][nt][2] * inv1); v1.y = f2tff(o[mt][nt][3] * inv1);
            *(float2*)(dst0 + nt * 8 + 2 * q) = v0;
            *(float2*)(dst1 + nt * 8 + 2 * q) = v1;
        }
    }
}

// ---------------- launch -------------------------------------------------------
extern "C" void kernel_launch(void* const* d_in, const int* in_sizes, int n_in,
                              void* d_out, int out_size)
{
    const float* x  = (const float*)d_in[0];
    const float* Wq = (const float*)d_in[1];
    const float* bq = (const float*)d_in[2];
    const float* Wk = (const float*)d_in[3];
    const float* bk = (const float*)d_in[4];
    const float* Wv = (const float*)d_in[5];
    const float* bv = (const float*)d_in[6];
    const float* Wo = (const float*)d_in[7];
    const float* bo = (const float*)d_in[8];

    float *qp, *kp, *vp, *cp, *xr, *wr;
    cudaGetSymbolAddress((void**)&qp, g_q);
    cudaGetSymbolAddress((void**)&kp, g_k);
    cudaGetSymbolAddress((void**)&vp, g_v);
    cudaGetSymbolAddress((void**)&cp, g_ctx);
    cudaGetSymbolAddress((void**)&xr, g_xr);
    cudaGetSymbolAddress((void**)&wr, g_wr);

    static bool attr_done = false;
    if (!attr_done) {
        cudaFuncSetAttribute(attn_mma,
                             cudaFuncAttributeMaxDynamicSharedMemorySize, ATTN_SMEM);
        attr_done = true;
    }

    // Pre-round x (1 launch) and all 4 weights (1 launch)
    const int xN4 = MROWS * EMB / 4;       // 2097152
    const int wN4 = EMB * EMB / 4;         // 262144
    roundcpy<<<1024, 256>>>((const float4*)x, (float4*)xr, xN4);
    roundcpy4<<<1024, 256>>>((const float4*)Wq, (const float4*)Wk,
                             (const float4*)Wv, (const float4*)Wo,
                             (float4*)wr, wN4);

    dim3 gemm_grid(EMB / 128, MROWS / 128);   // (8, 64)
    gemm_tf32<<<gemm_grid, 256>>>(xr, wr + 0*EMB*EMB, bq, qp, 1, QSCALE); // Q: interleaved+scaled
    gemm_tf32<<<gemm_grid, 256>>>(xr, wr + 1*EMB*EMB, bk, kp, 1, 1.0f);   // K: interleaved
    gemm_tf32<<<gemm_grid, 256>>>(xr, wr + 2*EMB*EMB, bv, vp, 2, 1.0f);   // V: natural

    dim3 attn_grid(SEQ / 128, BATCH * HEADS);  // (16, 64)
    attn_mma<<<attn_grid, 128, ATTN_SMEM>>>(qp, kp, vp, cp);

    gemm_tf32<<<gemm_grid, 256>>>(cp, wr + 3*EMB*EMB, bo, (float*)d_out, 0, 1.0f);
}

// round 16
// speedup vs baseline: 1.4873x; 1.4873x over previous
#include <cuda_runtime.h>
#include <cuda_bf16.h>
#include <math.h>

// Problem constants
#define BATCH 4
#define SEQ   2048
#define EMB   1024
#define HEADS 16
#define HDIM  64
#define MROWS (BATCH*SEQ)   // 8192

// ---------------- scratch (device globals; no allocation allowed) -------------
__device__ float g_q[BATCH*HEADS*SEQ*HDIM];    // [B,H,S,D] interleaved d, pre-scaled
__device__ float g_k[BATCH*HEADS*SEQ*HDIM];    // [B,H,S,D] interleaved d
__device__ float g_v[BATCH*HEADS*SEQ*HDIM];    // [B,H,S,D] natural
__device__ float g_ctx[BATCH*SEQ*EMB];         // [B,S,E]   pre-rounded
__device__ float g_xr[MROWS*EMB];              // x, tf32-rounded
__device__ float g_wr[4*EMB*EMB];              // Wq,Wk,Wv,Wo tf32-rounded

// ---------------- helpers ------------------------------------------------------
__device__ __forceinline__ unsigned f2tf(float x) {
    unsigned u;
    asm("cvt.rna.tf32.f32 %0, %1;" : "=r"(u) : "f"(x));
    return u;
}
__device__ __forceinline__ float f2tff(float x) {
    return __uint_as_float(f2tf(x));
}
__device__ __forceinline__ float ex2f(float x) {
    float y;
    asm("ex2.approx.f32 %0, %1;" : "=f"(y) : "f"(x));
    return y;
}
__device__ __forceinline__ void mma8(float c[4], const unsigned a[4], const unsigned b[2]) {
    asm volatile(
        "mma.sync.aligned.m16n8k8.row.col.f32.tf32.tf32.f32 "
        "{%0,%1,%2,%3}, {%4,%5,%6,%7}, {%8,%9}, {%0,%1,%2,%3};"
        : "+f"(c[0]), "+f"(c[1]), "+f"(c[2]), "+f"(c[3])
        : "r"(a[0]), "r"(a[1]), "r"(a[2]), "r"(a[3]),
          "r"(b[0]), "r"(b[1]));
}
__device__ __forceinline__ void cpa16(unsigned smem, const void* gmem) {
    asm volatile("cp.async.cg.shared.global [%0], [%1], 16;" :: "r"(smem), "l"(gmem));
}
__device__ __forceinline__ void cpa_commit() {
    asm volatile("cp.async.commit_group;");
}
__device__ __forceinline__ void cpa_wait1() {
    asm volatile("cp.async.wait_group 1;");
}
__device__ __forceinline__ void cpa_wait0() {
    asm volatile("cp.async.wait_group 0;");
}

// ---------------- pre-round kernels --------------------------------------------
__global__ __launch_bounds__(256) void roundcpy(
    const float4* __restrict__ src, float4* __restrict__ dst, int n4)
{
    int i = blockIdx.x * blockDim.x + threadIdx.x;
    int stride = gridDim.x * blockDim.x;
    for (; i < n4; i += stride) {
        float4 v = src[i];
        v.x = f2tff(v.x); v.y = f2tff(v.y);
        v.z = f2tff(v.z); v.w = f2tff(v.w);
        dst[i] = v;
    }
}

// One launch for all 4 weight matrices (dst contiguous in g_wr)
__global__ __launch_bounds__(256) void roundcpy4(
    const float4* __restrict__ s0, const float4* __restrict__ s1,
    const float4* __restrict__ s2, const float4* __restrict__ s3,
    float4* __restrict__ dst, int n4each)
{
    int i = blockIdx.x * blockDim.x + threadIdx.x;
    int stride = gridDim.x * blockDim.x;
    const int total = 4 * n4each;
    for (; i < total; i += stride) {
        int wsel = i / n4each;
        int off  = i - wsel * n4each;
        const float4* s = (wsel == 0) ? s0 : (wsel == 1) ? s1 : (wsel == 2) ? s2 : s3;
        float4 v = s[off];
        v.x = f2tff(v.x); v.y = f2tff(v.y);
        v.z = f2tff(v.z); v.w = f2tff(v.w);
        dst[i] = v;
    }
}

// ---------------- GEMM (tf32 MMA, BK=64 single-buffer): C = A @ W + bias ------
// Inputs pre-rounded. mode: 0 = plain row-major fp32 out;
// 1 = qkv scatter, d interleaved (pair-perm), scaled+rounded (Q/K);
// 2 = qkv scatter, natural d, rounded (V).
// BK=64 halves barrier count and exposed-load stalls vs BK=32.
#define AST 68     // 68 mod 32 == 4: same conflict-free 4g+q pattern as stride 36
#define BST 136
#define NKT (EMB / 64)   // 16 k-tiles
#define QSCALE 0.1803368801f    // (1/8) * log2(e)

__global__ __launch_bounds__(256, 2) void gemm_tf32(
    const float* __restrict__ A, const float* __restrict__ W,
    const float* __restrict__ bias, float* __restrict__ C,
    int mode, float scale)
{
    __shared__ float As[128 * AST];   // 128 x 64
    __shared__ float Bs[64 * BST];    // 64 x 128

    const int tid  = threadIdx.x;
    const int lane = tid & 31;
    const int wid  = tid >> 5;
    const int wr   = wid >> 2;      // 0..1
    const int wc   = wid & 3;       // 0..3
    const int g    = lane >> 2;     // 0..7
    const int q    = lane & 3;      // 0..3
    const int rowBase = blockIdx.y * 128;
    const int colBase = blockIdx.x * 128;

    const float* Ag = A + (size_t)rowBase * EMB;
    const float* Wg = W + colBase;

    float acc[4][4][4];
#pragma unroll
    for (int mt = 0; mt < 4; mt++)
#pragma unroll
        for (int nt = 0; nt < 4; nt++)
#pragma unroll
            for (int i = 0; i < 4; i++) acc[mt][nt][i] = 0.f;

    for (int kt = 0; kt < EMB; kt += 64) {
        // Stage A tile 128x64 (pure copy; inputs pre-rounded). 2048 float4.
#pragma unroll
        for (int i = 0; i < 8; i++) {
            int f  = tid + i * 256;
            int r  = f >> 4;           // row 0..127
            int c4 = f & 15;           // float4 col 0..15
            *(float4*)(&As[r * AST + c4 * 4]) =
                *(const float4*)(Ag + (size_t)r * EMB + kt + c4 * 4);
        }
        // Stage W tile 64x128. 2048 float4.
#pragma unroll
        for (int i = 0; i < 8; i++) {
            int f  = tid + i * 256;
            int r  = f >> 5;           // k-row 0..63
            int c4 = f & 31;           // float4 col 0..31
            *(float4*)(&Bs[r * BST + c4 * 4]) =
                *(const float4*)(Wg + (size_t)(kt + r) * EMB + c4 * 4);
        }
        __syncthreads();

#pragma unroll
        for (int kk = 0; kk < 8; kk++) {
            const int k0 = kk * 8;
            unsigned a[4][4], b[4][2];
#pragma unroll
            for (int mt = 0; mt < 4; mt++) {
                int row = wr * 64 + mt * 16 + g;
                const float* p = &As[row * AST + k0 + q];
                a[mt][0] = __float_as_uint(p[0]);
                a[mt][1] = __float_as_uint(p[8 * AST]);
                a[mt][2] = __float_as_uint(p[4]);
                a[mt][3] = __float_as_uint(p[8 * AST + 4]);
            }
#pragma unroll
            for (int nt = 0; nt < 4; nt++) {
                int col = wc * 32 + nt * 8 + g;
                const float* p = &Bs[(k0 + q) * BST + col];
                b[nt][0] = __float_as_uint(p[0]);
                b[nt][1] = __float_as_uint(p[4 * BST]);
            }
#pragma unroll
            for (int mt = 0; mt < 4; mt++)
#pragma unroll
                for (int nt = 0; nt < 4; nt++)
                    mma8(acc[mt][nt], a[mt], b[nt]);
        }
        __syncthreads();
    }

#pragma unroll
    for (int mt = 0; mt < 4; mt++) {
#pragma unroll
        for (int nt = 0; nt < 4; nt++) {
            int row = rowBase + wr * 64 + mt * 16 + g;
            int col = colBase + wc * 32 + nt * 8 + 2 * q;
            float e00 = acc[mt][nt][0] + bias[col];
            float e01 = acc[mt][nt][1] + bias[col + 1];
            float e10 = acc[mt][nt][2] + bias[col];
            float e11 = acc[mt][nt][3] + bias[col + 1];
            if (mode == 0) {
                float* base = C + (size_t)row * EMB + col;
                *(float2*)base = make_float2(e00, e01);
                *(float2*)(base + 8 * EMB) = make_float2(e10, e11);
            } else {
                e00 = f2tff(e00 * scale); e01 = f2tff(e01 * scale);
                e10 = f2tff(e10 * scale); e11 = f2tff(e11 * scale);
                int b0_ = row >> 11;
                int s0  = row & (SEQ - 1);
                int h   = col >> 6;
                int d   = col & (HDIM - 1);
                float* base = C + ((size_t)((b0_ * HEADS + h) * SEQ + s0)) * HDIM;
                if (mode == 1) {
                    // interleave perm within 8-group: w -> 2*(w&3) + (w>>2)
                    int grp = d & ~7;
                    int w0 = d & 7, w1 = w0 + 1;
                    int sl0 = grp + 2 * (w0 & 3) + (w0 >> 2);
                    int sl1 = grp + 2 * (w1 & 3) + (w1 >> 2);
                    base[sl0] = e00;             base[sl1] = e01;
                    base[8 * HDIM + sl0] = e10;  base[8 * HDIM + sl1] = e11;
                } else {
                    *(float2*)(base + d) = make_float2(e00, e01);
                    *(float2*)(base + 8 * HDIM + d) = make_float2(e10, e11);
                }
            }
        }
    }
}

// ---------------- Flash attention (tf32 MMA, v6 — unchanged from best) ---------
#define QST 72
#define KST 72
#define VST 68
#define ATTN_SMEM ((128*QST + 2*64*KST + 2*64*VST) * 4)   // 108544 B

__global__ __launch_bounds__(128) void attn_mma(
    const float* __restrict__ Q, const float* __restrict__ K,
    const float* __restrict__ V, float* __restrict__ O)
{
    extern __shared__ float sm[];
    float* Qs  = sm;                      // [128][QST]
    float* Kb0 = Qs + 128 * QST;          // [64][KST]
    float* Kb1 = Kb0 + 64 * KST;
    float* Vb0 = Kb1 + 64 * KST;          // [64][VST]
    float* Vb1 = Vb0 + 64 * VST;

    const int tid  = threadIdx.x;
    const int lane = tid & 31;
    const int w    = tid >> 5;        // warp 0..3 -> rows w*32..w*32+31
    const int g    = lane >> 2;       // 0..7
    const int q    = lane & 3;        // 0..3
    const int bh   = blockIdx.y;      // 0..63
    const int qBase = blockIdx.x * 128;
    const unsigned FULL = 0xffffffffu;

    const float* Qg = Q + ((size_t)bh * SEQ + qBase) * HDIM;
    const float* Kg = K + (size_t)bh * SEQ * HDIM;
    const float* Vg = V + (size_t)bh * SEQ * HDIM;

    const unsigned qs_a  = (unsigned)__cvta_generic_to_shared(Qs);
    const unsigned kb_a[2] = { (unsigned)__cvta_generic_to_shared(Kb0),
                               (unsigned)__cvta_generic_to_shared(Kb1) };
    const unsigned vb_a[2] = { (unsigned)__cvta_generic_to_shared(Vb0),
                               (unsigned)__cvta_generic_to_shared(Vb1) };

    // Q tile: 128x64 = 2048 16B chunks; 16 per thread
#pragma unroll
    for (int i = 0; i < 16; i++) {
        int f  = tid + i * 128;
        int r  = f >> 4;
        int c4 = f & 15;
        cpa16(qs_a + (r * QST + c4 * 4) * 4, Qg + (size_t)r * HDIM + c4 * 4);
    }
    // K/V tile 0
    {
        const float* kb = Kg;
        const float* vb = Vg;
#pragma unroll
        for (int i = 0; i < 8; i++) {
            int f  = tid + i * 128;
            int r  = f >> 4;
            int c4 = f & 15;
            cpa16(kb_a[0] + (r * KST + c4 * 4) * 4, kb + (size_t)r * HDIM + c4 * 4);
            cpa16(vb_a[0] + (r * VST + c4 * 4) * 4, vb + (size_t)r * HDIM + c4 * 4);
        }
    }
    cpa_commit();

    float o[2][8][4];
#pragma unroll
    for (int mt = 0; mt < 2; mt++)
#pragma unroll
        for (int nt = 0; nt < 8; nt++)
#pragma unroll
            for (int i = 0; i < 4; i++) o[mt][nt][i] = 0.f;
    float l[2][2] = {{0.f, 0.f}, {0.f, 0.f}};   // [mt][row-half]

    for (int t = 0; t < SEQ / 64; t++) {
        if (t < SEQ / 64 - 1) {
            const int nb = (t + 1) & 1;
            const float* kb = Kg + (size_t)(t + 1) * 64 * HDIM;
            const float* vb = Vg + (size_t)(t + 1) * 64 * HDIM;
#pragma unroll
            for (int i = 0; i < 8; i++) {
                int f  = tid + i * 128;
                int r  = f >> 4;
                int c4 = f & 15;
                cpa16(kb_a[nb] + (r * KST + c4 * 4) * 4, kb + (size_t)r * HDIM + c4 * 4);
                cpa16(vb_a[nb] + (r * VST + c4 * 4) * 4, vb + (size_t)r * HDIM + c4 * 4);
            }
            cpa_commit();
            cpa_wait1();
        } else {
            cpa_wait0();
        }
        __syncthreads();

        const float* Ks = (t & 1) ? Kb1 : Kb0;
        const float* Vs = (t & 1) ? Vb1 : Vb0;

        // ---- S = Qscaled @ K^T : 32 rows x 64 cols per warp ----
        float s[2][8][4];
#pragma unroll
        for (int mt = 0; mt < 2; mt++)
#pragma unroll
            for (int nt = 0; nt < 8; nt++)
#pragma unroll
                for (int i = 0; i < 4; i++) s[mt][nt][i] = 0.f;

#pragma unroll
        for (int kk = 0; kk < 8; kk++) {
            const int sl = kk * 8 + 2 * q;
            unsigned a[2][4];
#pragma unroll
            for (int mt = 0; mt < 2; mt++) {
                const int row = w * 32 + mt * 16 + g;
                float2 x0 = *(const float2*)&Qs[row * QST + sl];
                float2 x1 = *(const float2*)&Qs[(row + 8) * QST + sl];
                a[mt][0] = __float_as_uint(x0.x);
                a[mt][1] = __float_as_uint(x1.x);
                a[mt][2] = __float_as_uint(x0.y);
                a[mt][3] = __float_as_uint(x1.y);
            }
#pragma unroll
            for (int nt = 0; nt < 8; nt++) {
                float2 kv = *(const float2*)&Ks[(nt * 8 + g) * KST + sl];
                unsigned b[2];
                b[0] = __float_as_uint(kv.x);
                b[1] = __float_as_uint(kv.y);
                mma8(s[0][nt], a[0], b);
                mma8(s[1][nt], a[1], b);
            }
        }

        // ---- P = ex2(S); O += P @ V (C-frag == A-frag, no shuffles) ----
        float rs[2][2] = {{0.f, 0.f}, {0.f, 0.f}};
#pragma unroll
        for (int kk = 0; kk < 8; kk++) {
            const int t0 = kk * 8;
            unsigned a[2][4];
#pragma unroll
            for (int mt = 0; mt < 2; mt++) {
                float p0 = ex2f(s[mt][kk][0]);   // (row g,   t 2q)
                float p1 = ex2f(s[mt][kk][1]);   // (row g,   t 2q+1)
                float p2 = ex2f(s[mt][kk][2]);   // (row g+8, t 2q)
                float p3 = ex2f(s[mt][kk][3]);   // (row g+8, t 2q+1)
                rs[mt][0] += p0 + p1;
                rs[mt][1] += p2 + p3;
                a[mt][0] = f2tf(p0);
                a[mt][1] = f2tf(p2);
                a[mt][2] = f2tf(p1);
                a[mt][3] = f2tf(p3);
            }
#pragma unroll
            for (int nt = 0; nt < 8; nt++) {
                const int col = nt * 8 + g;
                unsigned b[2];
                b[0] = __float_as_uint(Vs[(t0 + 2 * q)     * VST + col]);
                b[1] = __float_as_uint(Vs[(t0 + 2 * q + 1) * VST + col]);
                mma8(o[0][nt], a[0], b);
                mma8(o[1][nt], a[1], b);
            }
        }

        // accumulate row sums (quad reduction)
#pragma unroll
        for (int mt = 0; mt < 2; mt++) {
#pragma unroll
            for (int hh = 0; hh < 2; hh++) {
                float r_ = rs[mt][hh];
                r_ += __shfl_xor_sync(FULL, r_, 1);
                r_ += __shfl_xor_sync(FULL, r_, 2);
                l[mt][hh] += r_;
            }
        }
        __syncthreads();   // all warps done with this buffer before its refill
    }

    // Write context in [B,S,E] layout, pre-rounded for the O-projection GEMM
    const int b_ = bh >> 4;
    const int h  = bh & 15;
#pragma unroll
    for (int mt = 0; mt < 2; mt++) {
        const float inv0 = 1.0f / l[mt][0];
        const float inv1 = 1.0f / l[mt][1];
        const int srow = qBase + w * 32 + mt * 16 + g;
        float* dst0 = O + ((size_t)(b_ * SEQ + srow)) * EMB + h * HDIM;
        float* dst1 = dst0 + (size_t)8 * EMB;
#pragma unroll
        for (int nt = 0; nt < 8; nt++) {
            float2 v0, v1;
            v0.x = f2tff(o[mt][nt][0] * inv0); v0.y = f2tff(o[mt][nt][1] * inv0);
            v1.x = f2tff(o[mt][nt][2] * inv1); v1.y = f2tff(o[mt][nt][3] * inv1);
            *(float2*)(dst0 + nt * 8 + 2 * q) = v0;
            *(float2*)(dst1 + nt * 8 + 2 * q) = v1;
        }
    }
}

// ---------------- launch -------------------------------------------------------
extern "C" void kernel_launch(void* const* d_in, const int* in_sizes, int n_in,
                              void* d_out, int out_size)
{
    const float* x  = (const float*)d_in[0];
    const float* Wq = (const float*)d_in[1];
    const float* bq = (const float*)d_in[2];
    const float* Wk = (const float*)d_in[3];
    const float* bk = (const float*)d_in[4];
    const float* Wv = (const float*)d_in[5];
    const float* bv = (const float*)d_in[6];
    const float* Wo = (const float*)d_in[7];
    const float* bo = (const float*)d_in[8];

    float *qp, *kp, *vp, *cp, *xr, *wr;
    cudaGetSymbolAddress((void**)&qp, g_q);
    cudaGetSymbolAddress((void**)&kp, g_k);
    cudaGetSymbolAddress((void**)&vp, g_v);
    cudaGetSymbolAddress((void**)&cp, g_ctx);
    cudaGetSymbolAddress((void**)&xr, g_xr);
    cudaGetSymbolAddress((void**)&wr, g_wr);

    static bool attr_done = false;
    if (!attr_done) {
        cudaFuncSetAttribute(attn_mma,
                             cudaFuncAttributeMaxDynamicSharedMemorySize, ATTN_SMEM);
        attr_done = true;
    }

    // Pre-round x (1 launch) and all 4 weights (1 launch)
    const int xN4 = MROWS * EMB / 4;       // 2097152
    const int wN4 = EMB * EMB / 4;         // 262144
    roundcpy<<<1024, 256>>>((const float4*)x, (float4*)xr, xN4);
    roundcpy4<<<1024, 256>>>((const float4*)Wq, (const float4*)Wk,
                             (const float4*)Wv, (const float4*)Wo,
                             (float4*)wr, wN4);

    dim3 gemm_grid(EMB / 128, MROWS / 128);   // (8, 64)
    gemm_tf32<<<gemm_grid, 256>>>(xr, wr + 0*EMB*EMB, bq, qp, 1, QSCALE); // Q: interleaved+scaled
    gemm_tf32<<<gemm_grid, 256>>>(xr, wr + 1*EMB*EMB, bk, kp, 1, 1.0f);   // K: interleaved
    gemm_tf32<<<gemm_grid, 256>>>(xr, wr + 2*EMB*EMB, bv, vp, 2, 1.0f);   // V: natural

    dim3 attn_grid(SEQ / 128, BATCH * HEADS);  // (16, 64)
    attn_mma<<<attn_grid, 128, ATTN_SMEM>>>(qp, kp, vp, cp);

    gemm_tf32<<<gemm_grid, 256>>>(cp, wr + 3*EMB*EMB, bo, (float*)d_out, 0, 1.0f);
}